// round 15
// baseline (speedup 1.0000x reference)
#include <cuda_runtime.h>
#include <math_constants.h>

// Shapes fixed by setup_inputs: N=8192, K=16
#define NQ     8192
#define KTOP   16
#define NSEG   32                // filter sub-slices
#define SSLEN  256               // candidates per sub-slice
#define SEG    16                // per-(query,subslice) admitted cap (mean ~1.3)
#define NGRP   8                 // threshold groups (top-2 each -> >=16 admits)
#define NSUB   4                 // sub-partials per group
#define GSUB   96                // candidates per sub-partial (8*4*96 = 3072)
#define GRIDB  128               // persistent blocks (<=148 SMs -> co-resident)
#define TPB    1024              // threads per block (8 warpgroups of 128)

// Static scratch (no runtime allocation allowed)
__device__ float4   g_cand[NQ];                // (cx, cy, -0.5|c|^2, 0)
__device__ float2   g_gmax2[NGRP * NSUB][NQ];  // per-(group,sub) top-2 of s
__device__ float2   g_pair[NQ * NSEG * SEG];   // admitted (s, idx-bits)
__device__ int      g_cnt[NQ][NSEG];           // per-(query,subslice) counts
__device__ float    g_term[KTOP * NQ];         // exp-terms, k-major
__device__ float    g_part[GRIDB];             // per-block partial sums
__device__ unsigned g_bar;                     // monotonic barrier counter

// score: s = x.c - 0.5|c|^2  (dist = |x|^2 - 2s; larger s == closer).
// Explicit FMA chain -> bitwise identical in gmax and filter phases.
__device__ __forceinline__ float s_of(float cx, float cy, float nh,
                                      float x1, float x2)
{
    return __fmaf_rn(x2, cy, __fmaf_rn(x1, cx, nh));
}

// candidate prep: identical FMA chain everywhere -> identical bits.
__device__ __forceinline__ float4 poly4(const float2* __restrict__ ch2,
                                        const float* __restrict__ M1,
                                        const float* __restrict__ M2, int i)
{
    float2 a = ch2[i];
    float p  = __fmul_rn(a.x, a.y);
    float y1 = __fmaf_rn(M1[1], a.y, __fmaf_rn(M1[2], a.x, __fmaf_rn(M1[3], p, M1[0])));
    float y2 = __fmaf_rn(M2[1], a.y, __fmaf_rn(M2[2], a.x, __fmaf_rn(M2[3], p, M2[0])));
    float nh = -0.5f * __fmaf_rn(y1, y1, __fmul_rn(y2, y2));
    return make_float4(y1, y2, nh, 0.0f);
}

// order-preserving float->uint key (monotone)
__device__ __forceinline__ unsigned fkey(float f)
{
    unsigned u = __float_as_uint(f);
    return u ^ ((unsigned)((int)u >> 31) | 0x80000000u);
}

// exact top-2 merge of 4 sub-partials per group; T = min over groups of m2.
// Guarantee: every group's true top-2 have s >= m2 >= T  ->  >=16 admits.
__device__ __forceinline__ float tmin_of(int j)
{
    float T = CUDART_INF_F;
#pragma unroll
    for (int g = 0; g < NGRP; ++g) {
        float m1 = -CUDART_INF_F, m2 = -CUDART_INF_F;
#pragma unroll
        for (int sb = 0; sb < NSUB; ++sb) {
            float2 p = g_gmax2[g * NSUB + sb][j];
            m2 = fmaxf(fmaxf(m2, p.y), fminf(m1, p.x));
            m1 = fmaxf(m1, p.x);
        }
        T = fminf(T, m2);
    }
    return T;
}

// Grid barrier: monotonic counter (graph-replay safe; R13-validated).
// All GRIDB blocks co-resident by construction -> no deadlock.
__device__ __forceinline__ void grid_barrier()
{
    __threadfence();
    __syncthreads();
    if (threadIdx.x == 0) {
        unsigned arrival = atomicAdd(&g_bar, 1u);
        unsigned target  = (arrival / GRIDB + 1u) * GRIDB;
        while (*(volatile unsigned*)&g_bar < target)
            __nanosleep(64);
    }
    __syncthreads();
}

// ---------------------------------------------------------------------------
// Persistent pipeline: the validated R11 kernels as phases.
// Block b: qc = b>>2 (256-query chunk), sg = b&3; warpgroup w (128 thr).
//   P1 gmax:   (qc, y = sg*8+w), QPT=2       -- validated mapping (32,32)x128
//   P2 filter: (qc, sl = sg*8+w), QPT=2      -- validated mapping (32,32)x128
//   P3 select: warp-per-query, 2 rounds      -- validated R11 logic verbatim
//   P4 terms:  block-owned 64 queries        -- validated R13 P4
// ---------------------------------------------------------------------------
__global__ __launch_bounds__(TPB, 1)
void mega_kernel(const float2* __restrict__ ch1, const float2* __restrict__ ch2,
                 const float* __restrict__ M1, const float* __restrict__ M2,
                 float* __restrict__ out)
{
    __shared__ __align__(16) float4 sc[2048];   // 32 KB staging (both phases)
    __shared__ float sred[TPB];                 // 4 KB reduce pad

    const int tid = threadIdx.x;
    const int b   = blockIdx.x;
    const int w   = tid >> 7;        // warpgroup 0..7
    const int wt  = tid & 127;       // thread within warpgroup
    const int qc  = b >> 2;          // query chunk 0..31 (256 queries)
    const int sg  = b & 3;           // slice group 0..3

    // ---- P0+P1: gmax. Stage this block's 8 sub-partials (768 cands) ----
    if (tid < 768)
        sc[tid] = poly4(ch2, M1, M2, sg * 768 + tid);
    {   // fused prep: candidate table for select's exp step
        int gt = b * TPB + tid;
        if (gt < NQ) g_cand[gt] = poly4(ch2, M1, M2, gt);
    }
    __syncthreads();

    {
        const int q0 = qc * 256 + wt, q1 = q0 + 128;
        const int y  = sg * 8 + w;               // sub-partial 0..31
        const float2 xa = ch1[q0];
        const float2 xb = ch1[q1];
        const float4* cp = &sc[w * GSUB];

        float m10 = -CUDART_INF_F, m20 = -CUDART_INF_F;
        float m11 = -CUDART_INF_F, m21 = -CUDART_INF_F;
#pragma unroll 8
        for (int t = 0; t < GSUB; ++t) {
            float4 c = cp[t];
            float s0 = s_of(c.x, c.y, c.z, xa.x, xa.y);
            float s1 = s_of(c.x, c.y, c.z, xb.x, xb.y);
            m20 = fmaxf(m20, fminf(m10, s0));  m10 = fmaxf(m10, s0);
            m21 = fmaxf(m21, fminf(m11, s1));  m21 = fmaxf(m21, fminf(m11, s1));
            m11 = fmaxf(m11, s1);
        }
        g_gmax2[y][q0] = make_float2(m10, m20);
        g_gmax2[y][q1] = make_float2(m11, m21);
    }

    grid_barrier();   // g_gmax2 complete device-wide

    // ---- P2: filter. Stage this block's 8 sub-slices (2048 cands) ----
    sc[tid]        = poly4(ch2, M1, M2, sg * 2048 + tid);
    sc[tid + TPB]  = poly4(ch2, M1, M2, sg * 2048 + tid + TPB);
    __syncthreads();

    {
        const int q0 = qc * 256 + wt, q1 = q0 + 128;
        const int sl = sg * 8 + w;
        const float T0 = tmin_of(q0), T1 = tmin_of(q1);
        const float2 xa = ch1[q0];
        const float2 xb = ch1[q1];
        const float4* cp = &sc[w * SSLEN];
        float2* p0 = &g_pair[(q0 * NSEG + sl) * SEG];
        float2* p1 = &g_pair[(q1 * NSEG + sl) * SEG];

        int c0 = 0, c1 = 0;
#pragma unroll 8
        for (int t = 0; t < SSLEN; ++t) {
            float4 c = cp[t];
            float s0 = s_of(c.x, c.y, c.z, xa.x, xa.y);
            float s1 = s_of(c.x, c.y, c.z, xb.x, xb.y);
            float fi = __int_as_float(sl * SSLEN + t);
            if (s0 >= T0) { p0[c0 & (SEG - 1)] = make_float2(s0, fi); ++c0; }
            if (s1 >= T1) { p1[c1 & (SEG - 1)] = make_float2(s1, fi); ++c1; }
        }
        g_cnt[q0][sl] = min(c0, SEG);
        g_cnt[q1][sl] = min(c1, SEG);
    }

    grid_barrier();   // g_pair / g_cnt complete device-wide

    // ---- P3: select + scrambled exp emission (R11 logic verbatim).
    // Warp gw handles queries gw and gw+4096. Lane l owns segment l.
    // 16 rounds of redux-max(key)+redux-min(idx) == (s desc, idx asc)
    // == lax.top_k. Scramble inverted: entry p of query j feeds target
    // n=(j&511)*16+p at k=j>>9; g_term write is coalesced per warp.
    {
        const float scale = -0.5f / 2.25f;   // -0.5/sigma2^2, sigma2=1.5
        const int gw   = b * 32 + (tid >> 5);
        const int lane = tid & 31;

#pragma unroll
        for (int r = 0; r < 2; ++r) {
            const int j = r * 4096 + gw;

            const int cn = g_cnt[j][lane];
            const float2* sp = &g_pair[(j * NSEG + lane) * SEG];

            float l[KTOP];
            int   li[KTOP];
#pragma unroll
            for (int m = 0; m < KTOP; ++m) { l[m] = -CUDART_INF_F; li[m] = 0x7fffffff; }

            for (int c = 0; c < cn; ++c) {
                float2 pr = sp[c];
                float s  = pr.x;
                int   ci = __float_as_int(pr.y);
                if (s > l[KTOP - 1]) {
#pragma unroll
                    for (int m = KTOP - 1; m >= 1; --m) {
                        bool up   = s > l[m - 1];
                        bool here = (!up) && (s > l[m]);
                        float nd  = up ? l[m - 1]  : (here ? s  : l[m]);
                        int   ni  = up ? li[m - 1] : (here ? ci : li[m]);
                        l[m] = nd; li[m] = ni;
                    }
                    if (s > l[0]) { l[0] = s; li[0] = ci; }
                }
            }

            int myidx = 0;
#pragma unroll
            for (int k = 0; k < KTOP; ++k) {
                unsigned key = fkey(l[0]);
                unsigned mx  = __reduce_max_sync(0xffffffffu, key);
                unsigned cnd = (key == mx) ? (unsigned)li[0] : 0xffffffffu;
                unsigned win = __reduce_min_sync(0xffffffffu, cnd);
                if (lane == k) myidx = (int)win;
                bool pop = (key == mx) && ((unsigned)li[0] == win);
#pragma unroll
                for (int m = 0; m < KTOP - 1; ++m) {
                    l[m]  = pop ? l[m + 1]  : l[m];
                    li[m] = pop ? li[m + 1] : li[m];
                }
                if (pop) { l[KTOP - 1] = -CUDART_INF_F; li[KTOP - 1] = 0x7fffffff; }
            }

            if (lane < KTOP) {
                const int n = ((j & 511) << 4) + lane;   // target query
                const int k = j >> 9;                    // target k-slot
                float4 c = g_cand[myidx];
                float2 x = ch1[n];
                float dy1 = x.x - c.x;
                float dy2 = x.y - c.y;
                g_term[k * NQ + n] =
                    __expf(scale * __fmaf_rn(dy2, dy2, __fmul_rn(dy1, dy1)));
            }
        }
    }

    grid_barrier();   // g_term complete device-wide

    // ---- P4: term-sum + log for own 64 queries (R13-validated) ----
    {
        const int k = tid >> 6, q = b * 64 + (tid & 63);
        sred[tid] = g_term[k * NQ + q];      // coalesced (q fastest)
        __syncthreads();
#pragma unroll
        for (int off = 8; off > 0; off >>= 1) {   // tree over k
            if (tid < off * 64) sred[tid] += sred[tid + off * 64];
            __syncthreads();
        }
        if (tid < 64) {
            float expD = sred[tid] * (1.0f / (float)NQ);
            sred[tid] = (expD != 0.0f) ? __logf(expD) : 0.0f;
        }
        __syncthreads();
#pragma unroll
        for (int off = 32; off > 0; off >>= 1) {  // tree over queries
            if (tid < off) sred[tid] += sred[tid + off];
            __syncthreads();
        }
        if (tid == 0) g_part[b] = sred[0];
    }

    grid_barrier();   // all partials visible

    // ---- P5: block 0 sums 128 partials (fixed order), writes -sum ----
    if (b == 0) {
        if (tid < GRIDB) sred[tid] = g_part[tid];
        __syncthreads();
#pragma unroll
        for (int off = GRIDB / 2; off > 0; off >>= 1) {
            if (tid < off) sred[tid] += sred[tid + off];
            __syncthreads();
        }
        if (tid == 0) out[0] = -sred[0];
    }
}

// ---------------------------------------------------------------------------
extern "C" void kernel_launch(void* const* d_in, const int* in_sizes, int n_in,
                              void* d_out, int out_size)
{
    const float2* ch1 = (const float2*)d_in[0];
    const float2* ch2 = (const float2*)d_in[1];
    const float*  M1  = (const float*)d_in[2];
    const float*  M2  = (const float*)d_in[3];
    float* out = (float*)d_out;

    mega_kernel<<<GRIDB, TPB>>>(ch1, ch2, M1, M2, out);
}

// round 16
// speedup vs baseline: 1.1649x; 1.1649x over previous
#include <cuda_runtime.h>
#include <math_constants.h>

// Shapes fixed by setup_inputs: N=8192, K=16
#define NQ     8192
#define KTOP   16
#define NSEG   32                // filter sub-slices
#define SSLEN  256               // candidates per sub-slice
#define SEG    16                // per-(query,subslice) admitted cap (mean ~1.3)
#define NGRP   8                 // threshold groups (top-2 each -> >=16 admits)
#define NSUB   4                 // sub-partials per group
#define GSUB   96                // candidates per sub-partial (8*4*96 = 3072)
#define FB     128               // threads per block
#define QPT    2                 // queries per thread (gmax/filter)
#define NRB    16                // reduce blocks (512 queries each)

// Static scratch (no runtime allocation allowed)
__device__ float4   g_cand[NQ];                // (cx, cy, -0.5|c|^2, 0)
__device__ float2   g_gmax2[NGRP * NSUB][NQ];  // per-(group,sub) top-2 of s
__device__ float2   g_pair[NQ * NSEG * SEG];   // admitted (s, idx-bits)
__device__ int      g_cnt[NQ][NSEG];           // per-(query,subslice) counts
__device__ float    g_term[KTOP * NQ];         // exp-terms, k-major
__device__ float    g_part[NRB];               // partial sums
__device__ unsigned g_done;                    // zero-init; atomicInc wraps

// score: s = x.c - 0.5|c|^2  (dist = |x|^2 - 2s; larger s == closer).
// Explicit FMA chain -> bitwise identical in gmax and filter.
__device__ __forceinline__ float s_of(float cx, float cy, float nh,
                                      float x1, float x2)
{
    return __fmaf_rn(x2, cy, __fmaf_rn(x1, cx, nh));
}

// candidate prep: poly(ch2[i]) and -0.5*|.|^2, explicit FMA chain so every
// kernel computing it inline produces identical bits.
__device__ __forceinline__ float4 poly4(const float2* __restrict__ ch2,
                                        const float* __restrict__ M1,
                                        const float* __restrict__ M2, int i)
{
    float2 a = ch2[i];
    float p  = __fmul_rn(a.x, a.y);
    float y1 = __fmaf_rn(M1[1], a.y, __fmaf_rn(M1[2], a.x, __fmaf_rn(M1[3], p, M1[0])));
    float y2 = __fmaf_rn(M2[1], a.y, __fmaf_rn(M2[2], a.x, __fmaf_rn(M2[3], p, M2[0])));
    float nh = -0.5f * __fmaf_rn(y1, y1, __fmul_rn(y2, y2));
    return make_float4(y1, y2, nh, 0.0f);
}

// order-preserving float->uint key (monotone)
__device__ __forceinline__ unsigned fkey(float f)
{
    unsigned u = __float_as_uint(f);
    return u ^ ((unsigned)((int)u >> 31) | 0x80000000u);
}

// ---------------------------------------------------------------------------
// Kernel 1 (validated): gmax. Block = (256 queries via 2/thread,
// sub-partial y). y = g*4+sub covers candidates [y*96, y*96+96).
// Branch-free top-2 per query. y==0 blocks also write g_cand (fused prep).
// ---------------------------------------------------------------------------
__global__ __launch_bounds__(FB)
void gmax_kernel(const float2* __restrict__ ch1, const float2* __restrict__ ch2,
                 const float* __restrict__ M1, const float* __restrict__ M2)
{
    __shared__ float4 sc[GSUB];

    const int tid = threadIdx.x;
    const int y   = blockIdx.y;
    const int qb  = blockIdx.x * (FB * QPT);

    if (tid < GSUB)
        sc[tid] = poly4(ch2, M1, M2, y * GSUB + tid);

    if (y == 0) {   // fused prep: candidate table used by select's exp step
        int i0 = qb + tid;
        g_cand[i0]      = poly4(ch2, M1, M2, i0);
        g_cand[i0 + FB] = poly4(ch2, M1, M2, i0 + FB);
    }
    __syncthreads();

    const int q0 = qb + tid, q1 = q0 + FB;
    const float2 xa = ch1[q0];
    const float2 xb = ch1[q1];

    float m10 = -CUDART_INF_F, m20 = -CUDART_INF_F;
    float m11 = -CUDART_INF_F, m21 = -CUDART_INF_F;
#pragma unroll 8
    for (int t = 0; t < GSUB; ++t) {
        float4 c = sc[t];
        float s0 = s_of(c.x, c.y, c.z, xa.x, xa.y);
        float s1 = s_of(c.x, c.y, c.z, xb.x, xb.y);
        m20 = fmaxf(m20, fminf(m10, s0));  m10 = fmaxf(m10, s0);
        m21 = fmaxf(m21, fminf(m11, s1));  m11 = fmaxf(m11, s1);
    }
    g_gmax2[y][q0] = make_float2(m10, m20);
    g_gmax2[y][q1] = make_float2(m11, m21);
}

// exact top-2 merge of 4 sub-partials per group; T = min over groups of m2.
// Guarantee: every group's true top-2 have s >= m2 >= T  ->  >=16 admits.
__device__ __forceinline__ float tmin_of(int j)
{
    float T = CUDART_INF_F;
#pragma unroll
    for (int g = 0; g < NGRP; ++g) {
        float m1 = -CUDART_INF_F, m2 = -CUDART_INF_F;
#pragma unroll
        for (int sb = 0; sb < NSUB; ++sb) {
            float2 p = g_gmax2[g * NSUB + sb][j];
            m2 = fmaxf(fmaxf(m2, p.y), fminf(m1, p.x));
            m1 = fmaxf(m1, p.x);
        }
        T = fminf(T, m2);
    }
    return T;
}

// ---------------------------------------------------------------------------
// Kernel 2: filter (+tmin fused), BITMASK TWO-PHASE. Scan each 32-cand
// word branch-free, recording admits as register mask bits (no store-path
// instructions in the hot loop). Drain each word's sparse bits ascending
// (__ffs) and recompute s from the SAME smem values with the SAME FMA
// chain -> bitwise-identical, admission order still ascending index.
// Register counters -> deterministic/stable.
// ---------------------------------------------------------------------------
__global__ __launch_bounds__(FB)
void filter_kernel(const float2* __restrict__ ch1, const float2* __restrict__ ch2,
                   const float* __restrict__ M1, const float* __restrict__ M2)
{
    __shared__ float4 sc[SSLEN];   // 4 KB

    const int tid = threadIdx.x;
    const int sl  = blockIdx.y;
    const int qb  = blockIdx.x * (FB * QPT);

    sc[tid]      = poly4(ch2, M1, M2, sl * SSLEN + tid);
    sc[tid + FB] = poly4(ch2, M1, M2, sl * SSLEN + tid + FB);
    __syncthreads();

    const int q0 = qb + tid, q1 = q0 + FB;
    const float T0 = tmin_of(q0), T1 = tmin_of(q1);
    const float2 xa = ch1[q0];
    const float2 xb = ch1[q1];
    float2* p0 = &g_pair[(q0 * NSEG + sl) * SEG];
    float2* p1 = &g_pair[(q1 * NSEG + sl) * SEG];

    int c0 = 0, c1 = 0;
    for (int w = 0; w < SSLEN / 32; ++w) {
        const float4* cp = &sc[w * 32];
        unsigned m0 = 0u, m1 = 0u;
#pragma unroll
        for (int t = 0; t < 32; ++t) {
            float4 c = cp[t];
            float s0 = s_of(c.x, c.y, c.z, xa.x, xa.y);
            float s1 = s_of(c.x, c.y, c.z, xb.x, xb.y);
            m0 |= (s0 >= T0) ? (1u << t) : 0u;
            m1 |= (s1 >= T1) ? (1u << t) : 0u;
        }
        while (m0) {                         // ascending t -> stable order
            int t = __ffs(m0) - 1;
            m0 &= m0 - 1;
            float4 c = cp[t];
            float s0 = s_of(c.x, c.y, c.z, xa.x, xa.y);
            p0[c0 & (SEG - 1)] =
                make_float2(s0, __int_as_float(sl * SSLEN + w * 32 + t));
            ++c0;
        }
        while (m1) {
            int t = __ffs(m1) - 1;
            m1 &= m1 - 1;
            float4 c = cp[t];
            float s1 = s_of(c.x, c.y, c.z, xb.x, xb.y);
            p1[c1 & (SEG - 1)] =
                make_float2(s1, __int_as_float(sl * SSLEN + w * 32 + t));
            ++c1;
        }
    }
    g_cnt[q0][sl] = min(c0, SEG);
    g_cnt[q1][sl] = min(c1, SEG);
}

// ---------------------------------------------------------------------------
// Kernel 3 (validated R11/R12): select + scrambled exp emission.
// One warp per query j; lane l owns segment l (ascending index order ->
// stable). 16 rounds of redux-max(key)+redux-min(idx) == (s desc, idx asc)
// == lax.top_k order. Scramble inverted: entry p of query j feeds target
// n = (j&511)*16 + p at k = j>>9; g_term write coalesced.
// ---------------------------------------------------------------------------
__global__ __launch_bounds__(FB)
void select_kernel(const float2* __restrict__ ch1)
{
    const float scale = -0.5f / 2.25f;   // -0.5 / sigma2^2, sigma2 = 1.5
    const int j    = (blockIdx.x * FB + threadIdx.x) >> 5;
    const int lane = threadIdx.x & 31;

    const int cn = g_cnt[j][lane];
    const float2* sp = &g_pair[(j * NSEG + lane) * SEG];

    float l[KTOP];
    int   li[KTOP];
#pragma unroll
    for (int m = 0; m < KTOP; ++m) { l[m] = -CUDART_INF_F; li[m] = 0x7fffffff; }

    for (int c = 0; c < cn; ++c) {
        float2 pr = sp[c];
        float s  = pr.x;
        int   ci = __float_as_int(pr.y);
        if (s > l[KTOP - 1]) {
#pragma unroll
            for (int m = KTOP - 1; m >= 1; --m) {
                bool up   = s > l[m - 1];
                bool here = (!up) && (s > l[m]);
                float nd  = up ? l[m - 1]  : (here ? s  : l[m]);
                int   ni  = up ? li[m - 1] : (here ? ci : li[m]);
                l[m] = nd; li[m] = ni;
            }
            if (s > l[0]) { l[0] = s; li[0] = ci; }
        }
    }

    int myidx = 0;   // lane p captures winner of round p
#pragma unroll
    for (int k = 0; k < KTOP; ++k) {
        unsigned key = fkey(l[0]);
        unsigned mx  = __reduce_max_sync(0xffffffffu, key);
        unsigned cnd = (key == mx) ? (unsigned)li[0] : 0xffffffffu;
        unsigned win = __reduce_min_sync(0xffffffffu, cnd);
        if (lane == k) myidx = (int)win;
        bool pop = (key == mx) && ((unsigned)li[0] == win);
#pragma unroll
        for (int m = 0; m < KTOP - 1; ++m) {
            l[m]  = pop ? l[m + 1]  : l[m];
            li[m] = pop ? li[m + 1] : li[m];
        }
        if (pop) { l[KTOP - 1] = -CUDART_INF_F; li[KTOP - 1] = 0x7fffffff; }
    }

    if (lane < KTOP) {
        const int n = ((j & 511) << 4) + lane;   // target query
        const int k = j >> 9;                    // target k-slot
        float4 c = g_cand[myidx];
        float2 x = ch1[n];
        float dy1 = x.x - c.x;
        float dy2 = x.y - c.y;
        g_term[k * NQ + n] =
            __expf(scale * __fmaf_rn(dy2, dy2, __fmul_rn(dy1, dy1)));
    }
}

// ---------------------------------------------------------------------------
// Kernel 4 (validated R12): term-sum + log + partials + fused final.
// Thread = query n; 16 coalesced loads (k-major), ascending-k sum
// (reference order), log, block tree-reduce. Last block (atomicInc wraps
// -> graph-replay safe) sums the 16 partials in fixed order, writes -sum.
// ---------------------------------------------------------------------------
__global__ __launch_bounds__(512)
void reduce_kernel(float* __restrict__ out)
{
    const int tid = threadIdx.x;
    const int n   = blockIdx.x * 512 + tid;

    float esum = 0.0f;
#pragma unroll
    for (int k = 0; k < KTOP; ++k)
        esum += g_term[k * NQ + n];

    float expD = esum * (1.0f / (float)NQ);
    float v = (expD != 0.0f) ? __logf(expD) : 0.0f;

    __shared__ float red[512];
    __shared__ bool  last;
    red[tid] = v;
    __syncthreads();
#pragma unroll
    for (int off = 256; off > 0; off >>= 1) {
        if (tid < off) red[tid] += red[tid + off];
        __syncthreads();
    }
    if (tid == 0) {
        g_part[blockIdx.x] = red[0];
        __threadfence();
        unsigned old = atomicInc(&g_done, NRB - 1);   // wraps to 0 on last
        last = (old == NRB - 1);
    }
    __syncthreads();

    if (last && tid < 32) {
        float s = (tid < NRB) ? g_part[tid] : 0.0f;
#pragma unroll
        for (int o = 16; o > 0; o >>= 1)
            s += __shfl_xor_sync(0xffffffffu, s, o);
        if (tid == 0) out[0] = -s;
    }
}

// ---------------------------------------------------------------------------
extern "C" void kernel_launch(void* const* d_in, const int* in_sizes, int n_in,
                              void* d_out, int out_size)
{
    const float2* ch1 = (const float2*)d_in[0];
    const float2* ch2 = (const float2*)d_in[1];
    const float*  M1  = (const float*)d_in[2];
    const float*  M2  = (const float*)d_in[3];
    float* out = (float*)d_out;

    dim3 ggrid(NQ / (FB * QPT), NGRP * NSUB);   // (32, 32)
    gmax_kernel<<<ggrid, FB>>>(ch1, ch2, M1, M2);

    dim3 fgrid(NQ / (FB * QPT), NSEG);          // (32, 32)
    filter_kernel<<<fgrid, FB>>>(ch1, ch2, M1, M2);

    select_kernel<<<NQ * 32 / FB, FB>>>(ch1);   // 2048 blocks, 1 warp/query

    reduce_kernel<<<NRB, 512>>>(out);           // 16 blocks, final fused
}